// round 2
// baseline (speedup 1.0000x reference)
#include <cuda_runtime.h>
#include <math.h>
#include <stdint.h>

#define NN 4096
#define INF 512
#define OUTF 256
#define NHEAD 4
#define HD 64

// ---------------- scratch (device globals; no allocation allowed) ----------------
__device__ float  g_h[NN * OUTF];      // 4 MB: h = X @ W^T
__device__ float4 g_E1[NN];            // exp(d_j) per head
__device__ float4 g_Ep[NN];            // exp(0.2 d_j)
__device__ float4 g_T [NN];            // exp(-s_i)  (threshold: e1 >= T  <=>  s+d >= 0)
__device__ float4 g_A1[NN];            // exp(s_i)
__device__ float4 g_Ap[NN];            // exp(0.2 s_i)
__device__ float4 g_R1[NN];            // exp(s_i)   / denom_i
__device__ float4 g_Rp[NN];            // exp(0.2s_i)/ denom_i

// ---------------- f32x2 packed FMA helpers (Blackwell FFMA2) ----------------
__device__ __forceinline__ unsigned long long pack2(float lo, float hi) {
    unsigned long long r;
    asm("mov.b64 %0, {%1,%2};" : "=l"(r) : "f"(lo), "f"(hi));
    return r;
}
__device__ __forceinline__ void unpack2(unsigned long long v, float& lo, float& hi) {
    asm("mov.b64 {%0,%1}, %2;" : "=f"(lo), "=f"(hi) : "l"(v));
}
__device__ __forceinline__ void ffma2(unsigned long long& d, unsigned long long a, unsigned long long b) {
    asm("fma.rn.f32x2 %0, %1, %2, %3;" : "=l"(d) : "l"(a), "l"(b), "l"(d));
}

// ======================= Kernel 1: h = X @ W^T =======================
// X [NN, INF], W [OUTF, INF] (both K-major). BM=64, BN=64, BK=16, 128 thr, 8x4 f32x2 micro.
#define K1_BK 16
#define K1_PAD 68
__global__ __launch_bounds__(128) void k1_gemm(const float* __restrict__ X,
                                               const float* __restrict__ W) {
    __shared__ float sA[K1_BK][K1_PAD];
    __shared__ float sB[K1_BK][K1_PAD];
    const int m0 = blockIdx.y * 64;
    const int n0 = blockIdx.x * 64;
    const int tid = threadIdx.x;
    const int rg = tid >> 4;   // 0..7  -> rows rg*8..+7
    const int cg = tid & 15;   // 0..15 -> cols cg*4..+3

    unsigned long long acc[8][2];
#pragma unroll
    for (int r = 0; r < 8; r++) { acc[r][0] = 0ull; acc[r][1] = 0ull; }

    for (int k0 = 0; k0 < INF; k0 += K1_BK) {
        __syncthreads();
#pragma unroll
        for (int l = 0; l < 2; l++) {
            int s = tid + l * 128;          // 256 float4 slots per tile
            int m = s >> 2, kq = s & 3;
            float4 va = *(const float4*)&X[(size_t)(m0 + m) * INF + k0 + kq * 4];
            sA[kq * 4 + 0][m] = va.x; sA[kq * 4 + 1][m] = va.y;
            sA[kq * 4 + 2][m] = va.z; sA[kq * 4 + 3][m] = va.w;
            float4 vb = *(const float4*)&W[(size_t)(n0 + m) * INF + k0 + kq * 4];
            sB[kq * 4 + 0][m] = vb.x; sB[kq * 4 + 1][m] = vb.y;
            sB[kq * 4 + 2][m] = vb.z; sB[kq * 4 + 3][m] = vb.w;
        }
        __syncthreads();
#pragma unroll
        for (int k = 0; k < K1_BK; k++) {
            float4 a0 = *(const float4*)&sA[k][rg * 8];
            float4 a1 = *(const float4*)&sA[k][rg * 8 + 4];
            float4 b  = *(const float4*)&sB[k][cg * 4];
            unsigned long long b20 = pack2(b.x, b.y);
            unsigned long long b21 = pack2(b.z, b.w);
            float ar[8] = {a0.x, a0.y, a0.z, a0.w, a1.x, a1.y, a1.z, a1.w};
#pragma unroll
            for (int r = 0; r < 8; r++) {
                unsigned long long a2 = pack2(ar[r], ar[r]);
                ffma2(acc[r][0], a2, b20);
                ffma2(acc[r][1], a2, b21);
            }
        }
    }
#pragma unroll
    for (int r = 0; r < 8; r++) {
        float x0, x1, x2, x3;
        unpack2(acc[r][0], x0, x1);
        unpack2(acc[r][1], x2, x3);
        float4 v = make_float4(x0, x1, x2, x3);
        *(float4*)&g_h[(size_t)(m0 + rg * 8 + r) * OUTF + n0 + cg * 4] = v;
    }
}

// ======================= Kernel 1b: per-node attention stats =======================
// one block per node, one warp per head. s = <h_i, a_src>, d = <h_i, a_dst>.
__global__ __launch_bounds__(128) void k1b_stats(const float* __restrict__ a) {
    const int i = blockIdx.x;
    const int head = threadIdx.x >> 5;
    const int lane = threadIdx.x & 31;
    float h0 = g_h[i * OUTF + head * HD + lane];
    float h1 = g_h[i * OUTF + head * HD + 32 + lane];
    const float* ah = a + head * 2 * HD;
    float s = h0 * ah[lane] + h1 * ah[32 + lane];
    float d = h0 * ah[HD + lane] + h1 * ah[HD + 32 + lane];
#pragma unroll
    for (int o = 16; o > 0; o >>= 1) {
        s += __shfl_xor_sync(0xffffffffu, s, o);
        d += __shfl_xor_sync(0xffffffffu, d, o);
    }
    if (lane == 0) {
        ((float*)&g_T [i])[head] = expf(-s);
        ((float*)&g_A1[i])[head] = expf(s);
        ((float*)&g_Ap[i])[head] = expf(0.2f * s);
        ((float*)&g_E1[i])[head] = expf(d);
        ((float*)&g_Ep[i])[head] = expf(0.2f * d);
    }
}

// ======================= Kernel 2: softmax denominators =======================
// denom_ih = exp(s)*S1 + exp(0.2s)*Sp  with S1 = sum over masked j with s+d>=0 of exp(d_j),
// Sp likewise with exp(0.2 d_j). Node tables (128 KB) staged in smem; one adj sweep.
#define K2_ROWS 32
#define K2_SMEM ((8 * NN + 72) * 4)
__global__ __launch_bounds__(256) void k2_denom(const float* __restrict__ adj) {
    extern __shared__ float sm[];
    float4* sE1 = (float4*)sm;                // NN float4
    float4* sEp = (float4*)(sm + 4 * NN);     // NN float4
    float*  red = sm + 8 * NN;                // 72 floats
    const int tid = threadIdx.x;

    for (int idx = tid; idx < NN; idx += 256) { sE1[idx] = g_E1[idx]; sEp[idx] = g_Ep[idx]; }
    __syncthreads();

    const int row0 = blockIdx.x * K2_ROWS;
    for (int r = 0; r < K2_ROWS; r++) {
        const int i = row0 + r;
        const float4 T = g_T[i];
        float S1x = 0.f, S1y = 0.f, S1z = 0.f, S1w = 0.f;
        float Spx = 0.f, Spy = 0.f, Spz = 0.f, Spw = 0.f;
        const float* arow = adj + (size_t)i * NN;
#pragma unroll
        for (int u = 0; u < NN / 256; u++) {
            int j = tid + u * 256;
            float av = arow[j];
            if (av > 0.1f) {
                float4 e1 = sE1[j], ep = sEp[j];
                if (e1.x >= T.x) S1x += e1.x; else Spx += ep.x;
                if (e1.y >= T.y) S1y += e1.y; else Spy += ep.y;
                if (e1.z >= T.z) S1z += e1.z; else Spz += ep.z;
                if (e1.w >= T.w) S1w += e1.w; else Spw += ep.w;
            }
        }
        float vals[8] = {S1x, S1y, S1z, S1w, Spx, Spy, Spz, Spw};
#pragma unroll
        for (int v = 0; v < 8; v++) {
            float x = vals[v];
#pragma unroll
            for (int o = 16; o > 0; o >>= 1) x += __shfl_xor_sync(0xffffffffu, x, o);
            if ((tid & 31) == 0) red[(tid >> 5) * 8 + v] = x;
        }
        __syncthreads();
        if (tid < 8) {
            float x = 0.f;
#pragma unroll
            for (int w = 0; w < 8; w++) x += red[w * 8 + tid];
            red[64 + tid] = x;
        }
        __syncthreads();
        if (tid < 4) {
            float a1 = ((const float*)&g_A1[i])[tid];
            float ap = ((const float*)&g_Ap[i])[tid];
            float den = a1 * red[64 + tid] + ap * red[64 + 4 + tid];
            float inv = (den > 0.f) ? 1.f / den : 0.f;   // fully-masked row -> attention 0
            ((float*)&g_R1[i])[tid] = a1 * inv;
            ((float*)&g_Rp[i])[tid] = ap * inv;
        }
        __syncthreads();
    }
}

// ======================= Kernel 3: out = att_mean @ h + bias =======================
// BM=64 rows, BN=128 cols, Jt=64. 128 threads, 8x8 micro (f32x2 packed).
// w tile computed on the fly from factored attention, adj mask read once here.
#define K3_BM 64
#define K3_BN 128
#define K3_JT 64
#define SWS 72
#define K3_SMEM ((K3_JT * SWS + K3_JT * K3_BN + 3 * 64 * 4) * 4)
__global__ __launch_bounds__(128) void k3_out(const float* __restrict__ adj,
                                              const float* __restrict__ bias,
                                              float* __restrict__ out) {
    extern __shared__ float sm3[];
    float*  sW  = sm3;                                        // [Jt][SWS] (w transposed: [j][r])
    float*  sH  = sm3 + K3_JT * SWS;                          // [Jt][BN]
    float4* sT  = (float4*)(sm3 + K3_JT * SWS + K3_JT * K3_BN);
    float4* sR1 = sT + 64;
    float4* sRp = sR1 + 64;

    const int tid = threadIdx.x;
    const int row0 = blockIdx.y * K3_BM;
    const int c0 = blockIdx.x * K3_BN;

    if (tid < 64) {
        int i = row0 + tid;
        sT[tid] = g_T[i]; sR1[tid] = g_R1[i]; sRp[tid] = g_Rp[i];
    }
    const int jl = tid & 63;    // w-phase: this thread's j within tile
    const int half = tid >> 6;  // w-phase: row half
    const int rg = tid >> 4;    // gemm: 0..7
    const int cg = tid & 15;    // gemm: 0..15

    unsigned long long acc[8][4];
#pragma unroll
    for (int r = 0; r < 8; r++)
#pragma unroll
        for (int p = 0; p < 4; p++) acc[r][p] = 0ull;

    __syncthreads();

    for (int j0 = 0; j0 < NN; j0 += K3_JT) {
        float4 e1 = g_E1[j0 + jl];
        float4 ep = g_Ep[j0 + jl];
        // ---- compute attention-weight tile w[j][r] (this thread: fixed j, 32 rows) ----
#pragma unroll 8
        for (int rr = 0; rr < 32; rr++) {
            int r = half * 32 + rr;
            float av = adj[(size_t)(row0 + r) * NN + j0 + jl];
            float w = 0.f;
            if (av > 0.1f) {
                float4 T = sT[r], R1 = sR1[r], Rp = sRp[r];
                float s0 = (e1.x >= T.x) ? R1.x * e1.x : Rp.x * ep.x;
                float s1 = (e1.y >= T.y) ? R1.y * e1.y : Rp.y * ep.y;
                float s2 = (e1.z >= T.z) ? R1.z * e1.z : Rp.z * ep.z;
                float s3 = (e1.w >= T.w) ? R1.w * e1.w : Rp.w * ep.w;
                w = 0.25f * ((s0 + s1) + (s2 + s3));
            }
            sW[jl * SWS + r] = w;
        }
        // ---- load h tile [Jt][BN] ----
#pragma unroll
        for (int l = 0; l < 16; l++) {
            int s = tid + l * 128;      // 2048 float4 slots
            int j = s >> 5, c4 = s & 31;
            *(float4*)&sH[j * K3_BN + c4 * 4] =
                *(const float4*)&g_h[(size_t)(j0 + j) * OUTF + c0 + c4 * 4];
        }
        __syncthreads();
        // ---- GEMM: 8x8 micro, f32x2 ----
#pragma unroll 4
        for (int j = 0; j < K3_JT; j++) {
            float4 a0 = *(const float4*)&sW[j * SWS + rg * 8];
            float4 a1 = *(const float4*)&sW[j * SWS + rg * 8 + 4];
            float4 b0 = *(const float4*)&sH[j * K3_BN + cg * 8];
            float4 b1 = *(const float4*)&sH[j * K3_BN + cg * 8 + 4];
            unsigned long long b2[4] = {pack2(b0.x, b0.y), pack2(b0.z, b0.w),
                                        pack2(b1.x, b1.y), pack2(b1.z, b1.w)};
            float ar[8] = {a0.x, a0.y, a0.z, a0.w, a1.x, a1.y, a1.z, a1.w};
#pragma unroll
            for (int r = 0; r < 8; r++) {
                unsigned long long a2 = pack2(ar[r], ar[r]);
#pragma unroll
                for (int p = 0; p < 4; p++) ffma2(acc[r][p], a2, b2[p]);
            }
        }
        __syncthreads();
    }
    // ---- epilogue: + bias ----
#pragma unroll
    for (int r = 0; r < 8; r++) {
        int orow = row0 + rg * 8 + r;
        int cc = c0 + cg * 8;
        float o[8];
        unpack2(acc[r][0], o[0], o[1]);
        unpack2(acc[r][1], o[2], o[3]);
        unpack2(acc[r][2], o[4], o[5]);
        unpack2(acc[r][3], o[6], o[7]);
        float4 v0 = make_float4(o[0] + bias[cc + 0], o[1] + bias[cc + 1],
                                o[2] + bias[cc + 2], o[3] + bias[cc + 3]);
        float4 v1 = make_float4(o[4] + bias[cc + 4], o[5] + bias[cc + 5],
                                o[6] + bias[cc + 6], o[7] + bias[cc + 7]);
        *(float4*)&out[(size_t)orow * OUTF + cc] = v0;
        *(float4*)&out[(size_t)orow * OUTF + cc + 4] = v1;
    }
}

// ======================= launch =======================
extern "C" void kernel_launch(void* const* d_in, const int* in_sizes, int n_in,
                              void* d_out, int out_size) {
    const float* features = (const float*)d_in[0];
    const float* adj      = (const float*)d_in[1];
    const float* W        = (const float*)d_in[2];
    const float* a        = (const float*)d_in[3];
    const float* bias     = (const float*)d_in[4];
    float* out = (float*)d_out;

    cudaFuncSetAttribute(k2_denom, cudaFuncAttributeMaxDynamicSharedMemorySize, K2_SMEM);
    cudaFuncSetAttribute(k3_out,   cudaFuncAttributeMaxDynamicSharedMemorySize, K3_SMEM);

    k1_gemm<<<dim3(OUTF / 64, NN / 64), 128>>>(features, W);
    k1b_stats<<<NN, 128>>>(a);
    k2_denom<<<NN / K2_ROWS, 256, K2_SMEM>>>(adj);
    k3_out<<<dim3(OUTF / K3_BN, NN / K3_BM), 128, K3_SMEM>>>(adj, bias, out);
}

// round 6
// speedup vs baseline: 1.4208x; 1.4208x over previous
#include <cuda_runtime.h>
#include <math.h>
#include <stdint.h>

#define NN 4096
#define INF 512
#define OUTF 256
#define NHEAD 4
#define HD 64

// ---------------- scratch (device globals; no allocation allowed) ----------------
__device__ float  g_h[NN * OUTF];      // 4 MB: h = X @ W^T
__device__ float4 g_E1[NN];            // exp(d_j) per head
__device__ float4 g_Ep[NN];            // exp(0.2 d_j)
__device__ float4 g_T [NN];            // exp(-s_i)  (threshold: e1 >= T  <=>  s+d >= 0)
__device__ float4 g_A1[NN];            // exp(s_i)
__device__ float4 g_Ap[NN];            // exp(0.2 s_i)
__device__ float4 g_R1[NN];            // exp(s_i)   / denom_i
__device__ float4 g_Rp[NN];            // exp(0.2s_i)/ denom_i

#define K3_SPLIT 8
__device__ float g_part[K3_SPLIT * NN * OUTF];   // 32 MB split-K partials

// ---------------- f32x2 packed FMA helpers (Blackwell FFMA2) ----------------
__device__ __forceinline__ unsigned long long pack2(float lo, float hi) {
    unsigned long long r;
    asm("mov.b64 %0, {%1,%2};" : "=l"(r) : "f"(lo), "f"(hi));
    return r;
}
__device__ __forceinline__ void unpack2(unsigned long long v, float& lo, float& hi) {
    asm("mov.b64 {%0,%1}, %2;" : "=f"(lo), "=f"(hi) : "l"(v));
}
__device__ __forceinline__ void ffma2(unsigned long long& d, unsigned long long a, unsigned long long b) {
    asm("fma.rn.f32x2 %0, %1, %2, %3;" : "=l"(d) : "l"(a), "l"(b), "l"(d));
}

// ======================= Kernel 1: h = X @ W^T =======================
#define K1_BK 16
#define K1_PAD 68
__global__ __launch_bounds__(128) void k1_gemm(const float* __restrict__ X,
                                               const float* __restrict__ W) {
    __shared__ float sA[K1_BK][K1_PAD];
    __shared__ float sB[K1_BK][K1_PAD];
    const int m0 = blockIdx.y * 64;
    const int n0 = blockIdx.x * 64;
    const int tid = threadIdx.x;
    const int rg = tid >> 4;
    const int cg = tid & 15;

    unsigned long long acc[8][2];
#pragma unroll
    for (int r = 0; r < 8; r++) { acc[r][0] = 0ull; acc[r][1] = 0ull; }

    for (int k0 = 0; k0 < INF; k0 += K1_BK) {
        __syncthreads();
#pragma unroll
        for (int l = 0; l < 2; l++) {
            int s = tid + l * 128;
            int m = s >> 2, kq = s & 3;
            float4 va = *(const float4*)&X[(size_t)(m0 + m) * INF + k0 + kq * 4];
            sA[kq * 4 + 0][m] = va.x; sA[kq * 4 + 1][m] = va.y;
            sA[kq * 4 + 2][m] = va.z; sA[kq * 4 + 3][m] = va.w;
            float4 vb = *(const float4*)&W[(size_t)(n0 + m) * INF + k0 + kq * 4];
            sB[kq * 4 + 0][m] = vb.x; sB[kq * 4 + 1][m] = vb.y;
            sB[kq * 4 + 2][m] = vb.z; sB[kq * 4 + 3][m] = vb.w;
        }
        __syncthreads();
#pragma unroll
        for (int k = 0; k < K1_BK; k++) {
            float4 a0 = *(const float4*)&sA[k][rg * 8];
            float4 a1 = *(const float4*)&sA[k][rg * 8 + 4];
            float4 b  = *(const float4*)&sB[k][cg * 4];
            unsigned long long b20 = pack2(b.x, b.y);
            unsigned long long b21 = pack2(b.z, b.w);
            float ar[8] = {a0.x, a0.y, a0.z, a0.w, a1.x, a1.y, a1.z, a1.w};
#pragma unroll
            for (int r = 0; r < 8; r++) {
                unsigned long long a2 = pack2(ar[r], ar[r]);
                ffma2(acc[r][0], a2, b20);
                ffma2(acc[r][1], a2, b21);
            }
        }
    }
#pragma unroll
    for (int r = 0; r < 8; r++) {
        float x0, x1, x2, x3;
        unpack2(acc[r][0], x0, x1);
        unpack2(acc[r][1], x2, x3);
        float4 v = make_float4(x0, x1, x2, x3);
        *(float4*)&g_h[(size_t)(m0 + rg * 8 + r) * OUTF + n0 + cg * 4] = v;
    }
}

// ======================= Kernel 1b: per-node attention stats =======================
__global__ __launch_bounds__(128) void k1b_stats(const float* __restrict__ a) {
    const int i = blockIdx.x;
    const int head = threadIdx.x >> 5;
    const int lane = threadIdx.x & 31;
    float h0 = g_h[i * OUTF + head * HD + lane];
    float h1 = g_h[i * OUTF + head * HD + 32 + lane];
    const float* ah = a + head * 2 * HD;
    float s = h0 * ah[lane] + h1 * ah[32 + lane];
    float d = h0 * ah[HD + lane] + h1 * ah[HD + 32 + lane];
#pragma unroll
    for (int o = 16; o > 0; o >>= 1) {
        s += __shfl_xor_sync(0xffffffffu, s, o);
        d += __shfl_xor_sync(0xffffffffu, d, o);
    }
    if (lane == 0) {
        ((float*)&g_T [i])[head] = expf(-s);
        ((float*)&g_A1[i])[head] = expf(s);
        ((float*)&g_Ap[i])[head] = expf(0.2f * s);
        ((float*)&g_E1[i])[head] = expf(d);
        ((float*)&g_Ep[i])[head] = expf(0.2f * d);
    }
}

// ======================= Kernel 2: softmax denominators =======================
#define K2_ROWS 32
#define K2_SMEM ((8 * NN + 72) * 4)
__global__ __launch_bounds__(256) void k2_denom(const float* __restrict__ adj) {
    extern __shared__ float sm[];
    float4* sE1 = (float4*)sm;
    float4* sEp = (float4*)(sm + 4 * NN);
    float*  red = sm + 8 * NN;
    const int tid = threadIdx.x;

    for (int idx = tid; idx < NN; idx += 256) { sE1[idx] = g_E1[idx]; sEp[idx] = g_Ep[idx]; }
    __syncthreads();

    const int row0 = blockIdx.x * K2_ROWS;
    for (int r = 0; r < K2_ROWS; r++) {
        const int i = row0 + r;
        const float4 T = g_T[i];
        float S1x = 0.f, S1y = 0.f, S1z = 0.f, S1w = 0.f;
        float Spx = 0.f, Spy = 0.f, Spz = 0.f, Spw = 0.f;
        const float* arow = adj + (size_t)i * NN;
#pragma unroll
        for (int u = 0; u < NN / 256; u++) {
            int j = tid + u * 256;
            float av = arow[j];
            if (av > 0.1f) {
                float4 e1 = sE1[j], ep = sEp[j];
                if (e1.x >= T.x) S1x += e1.x; else Spx += ep.x;
                if (e1.y >= T.y) S1y += e1.y; else Spy += ep.y;
                if (e1.z >= T.z) S1z += e1.z; else Spz += ep.z;
                if (e1.w >= T.w) S1w += e1.w; else Spw += ep.w;
            }
        }
        float vals[8] = {S1x, S1y, S1z, S1w, Spx, Spy, Spz, Spw};
#pragma unroll
        for (int v = 0; v < 8; v++) {
            float x = vals[v];
#pragma unroll
            for (int o = 16; o > 0; o >>= 1) x += __shfl_xor_sync(0xffffffffu, x, o);
            if ((tid & 31) == 0) red[(tid >> 5) * 8 + v] = x;
        }
        __syncthreads();
        if (tid < 8) {
            float x = 0.f;
#pragma unroll
            for (int w = 0; w < 8; w++) x += red[w * 8 + tid];
            red[64 + tid] = x;
        }
        __syncthreads();
        if (tid < 4) {
            float a1 = ((const float*)&g_A1[i])[tid];
            float ap = ((const float*)&g_Ap[i])[tid];
            float den = a1 * red[64 + tid] + ap * red[64 + 4 + tid];
            float inv = (den > 0.f) ? 1.f / den : 0.f;
            ((float*)&g_R1[i])[tid] = a1 * inv;
            ((float*)&g_Rp[i])[tid] = ap * inv;
        }
        __syncthreads();
    }
}

// ======================= Kernel 3: split-K  part[s] = att_mean[:, s-range] @ h =======================
// grid (2, 64, 8). BM=64 rows, BN=128 cols, Jt=64, 512 j per split.
// sW layout transposed: sW[r][j], odd row stride 65 (conflict-free STS in w-phase,
// broadcast LDS.32 a-reads in GEMM). b-reads: two contiguous LDS.128 halves.
#define K3_BM 64
#define K3_BN 128
#define K3_JT 64
#define K3_JPS (NN / K3_SPLIT)
#define SWS 65
#define K3_SMEM ((K3_JT * SWS + K3_JT * K3_BN + 3 * 64 * 4) * 4)
__global__ __launch_bounds__(128, 4) void k3_out(const float* __restrict__ adj) {
    extern __shared__ float sm3[];
    float*  sW  = sm3;                                        // [64 rows][65] (r-major)
    float*  sH  = sm3 + K3_JT * SWS;                          // [Jt][BN]
    float4* sT  = (float4*)(sm3 + K3_JT * SWS + K3_JT * K3_BN);
    float4* sR1 = sT + 64;
    float4* sRp = sR1 + 64;

    const int tid = threadIdx.x;
    const int row0 = blockIdx.y * K3_BM;
    const int c0 = blockIdx.x * K3_BN;
    const int split = blockIdx.z;
    const int jbeg = split * K3_JPS;

    if (tid < 64) {
        int i = row0 + tid;
        sT[tid] = g_T[i]; sR1[tid] = g_R1[i]; sRp[tid] = g_Rp[i];
    }
    const int jl = tid & 63;    // w-phase: this thread's j within tile
    const int half = tid >> 6;  // w-phase: row half
    const int rg = tid >> 4;    // gemm: 0..7
    const int cg = tid & 15;    // gemm: 0..15

    unsigned long long acc[8][4];
#pragma unroll
    for (int r = 0; r < 8; r++)
#pragma unroll
        for (int p = 0; p < 4; p++) acc[r][p] = 0ull;

    __syncthreads();

    for (int jt = 0; jt < K3_JPS / K3_JT; jt++) {
        const int j0 = jbeg + jt * K3_JT;
        float4 e1 = g_E1[j0 + jl];
        float4 ep = g_Ep[j0 + jl];
        // ---- attention-weight tile: w[r][j] ----
#pragma unroll 8
        for (int rr = 0; rr < 32; rr++) {
            int r = half * 32 + rr;
            float av = adj[(size_t)(row0 + r) * NN + j0 + jl];
            float w = 0.f;
            if (av > 0.1f) {
                float4 T = sT[r], R1 = sR1[r], Rp = sRp[r];
                float s0 = (e1.x >= T.x) ? R1.x * e1.x : Rp.x * ep.x;
                float s1 = (e1.y >= T.y) ? R1.y * e1.y : Rp.y * ep.y;
                float s2 = (e1.z >= T.z) ? R1.z * e1.z : Rp.z * ep.z;
                float s3 = (e1.w >= T.w) ? R1.w * e1.w : Rp.w * ep.w;
                w = 0.25f * ((s0 + s1) + (s2 + s3));
            }
            sW[r * SWS + jl] = w;   // lanes: consecutive jl -> conflict-free
        }
        // ---- h tile [Jt][BN] ----
#pragma unroll
        for (int l = 0; l < 16; l++) {
            int s = tid + l * 128;
            int j = s >> 5, c4 = s & 31;
            *(float4*)&sH[j * K3_BN + c4 * 4] =
                *(const float4*)&g_h[(size_t)(j0 + j) * OUTF + c0 + c4 * 4];
        }
        __syncthreads();
        // ---- GEMM: rows rg*8..+7, cols {cg*4..+3, 64+cg*4..+3} ----
#pragma unroll 4
        for (int j = 0; j < K3_JT; j++) {
            float ar[8];
#pragma unroll
            for (int r = 0; r < 8; r++) ar[r] = sW[(rg * 8 + r) * SWS + j];  // broadcast
            ulonglong2 b0 = *(const ulonglong2*)&sH[j * K3_BN + cg * 4];
            ulonglong2 b1 = *(const ulonglong2*)&sH[j * K3_BN + 64 + cg * 4];
#pragma unroll
            for (int r = 0; r < 8; r++) {
                unsigned long long a2 = pack2(ar[r], ar[r]);
                ffma2(acc[r][0], a2, b0.x);
                ffma2(acc[r][1], a2, b0.y);
                ffma2(acc[r][2], a2, b1.x);
                ffma2(acc[r][3], a2, b1.y);
            }
        }
        __syncthreads();
    }
    // ---- write split partial ----
    float* pbase = g_part + (size_t)split * NN * OUTF;
#pragma unroll
    for (int r = 0; r < 8; r++) {
        int orow = row0 + rg * 8 + r;
        float o[8];
        unpack2(acc[r][0], o[0], o[1]);
        unpack2(acc[r][1], o[2], o[3]);
        unpack2(acc[r][2], o[4], o[5]);
        unpack2(acc[r][3], o[6], o[7]);
        *(float4*)&pbase[(size_t)orow * OUTF + c0 + cg * 4] =
            make_float4(o[0], o[1], o[2], o[3]);
        *(float4*)&pbase[(size_t)orow * OUTF + c0 + 64 + cg * 4] =
            make_float4(o[4], o[5], o[6], o[7]);
    }
}

// ======================= Kernel 4: reduce splits + bias =======================
__global__ __launch_bounds__(256) void k4_reduce(const float* __restrict__ bias,
                                                 float* __restrict__ out) {
    int idx = blockIdx.x * 256 + threadIdx.x;          // float4 index
    int col4 = idx & (OUTF / 4 - 1);
    float4 s = ((const float4*)bias)[col4];
    const float4* p = (const float4*)g_part;
#pragma unroll
    for (int k = 0; k < K3_SPLIT; k++) {
        float4 v = p[(size_t)k * (NN * OUTF / 4) + idx];
        s.x += v.x; s.y += v.y; s.z += v.z; s.w += v.w;
    }
    ((float4*)out)[idx] = s;
}

// ======================= launch =======================
extern "C" void kernel_launch(void* const* d_in, const int* in_sizes, int n_in,
                              void* d_out, int out_size) {
    const float* features = (const float*)d_in[0];
    const float* adj      = (const float*)d_in[1];
    const float* W        = (const float*)d_in[2];
    const float* a        = (const float*)d_in[3];
    const float* bias     = (const float*)d_in[4];
    float* out = (float*)d_out;

    cudaFuncSetAttribute(k2_denom, cudaFuncAttributeMaxDynamicSharedMemorySize, K2_SMEM);
    cudaFuncSetAttribute(k3_out,   cudaFuncAttributeMaxDynamicSharedMemorySize, K3_SMEM);

    k1_gemm<<<dim3(OUTF / 64, NN / 64), 128>>>(features, W);
    k1b_stats<<<NN, 128>>>(a);
    k2_denom<<<NN / K2_ROWS, 256, K2_SMEM>>>(adj);
    k3_out<<<dim3(OUTF / K3_BN, NN / K3_BM, K3_SPLIT), 128, K3_SMEM>>>(adj);
    k4_reduce<<<NN * OUTF / 4 / 256, 256>>>(bias, out);
}